// round 15
// baseline (speedup 1.0000x reference)
#include <cuda_runtime.h>
#include <cuda_bf16.h>
#include <cstdint>
#include <cstddef>

// ============================================================================
// ClassicalAttentionLayer, round 15: all GEMMs on 128x128 tiles (64x32 warp
// tiles, 96 KB smem, __launch_bounds__(256,2) -> 2 CTAs/SM) + fused
// reduce+mirror for x^T x.
//   out[r,d] = (colsum_d + (x @ M)[r,d]/8192) / (8192 + rowsum_r)
//   M = G H,  G = Wq^T Wk,  H = (x^T x) Wv^T
//   rowsum_r = x_r . w / 8192,  w = G xsum
//   colsum = Wv @ xsum (exact fp32), xsum = column sums of x (exact fp32)
// Critical path (stream 0): cvt_transpose(x) -> xtx(syrk, 144 CTAs) ->
// reduce+mirror -> Ht -> reduce -> Mt -> reduce -> final.
// Side: conversions, stats, G.
// ============================================================================

#define NROWS 8192
#define DMODEL 1024

__device__ __nv_bfloat16 g_xb [(size_t)NROWS * DMODEL];   // x bf16 row-major
__device__ __nv_bfloat16 g_xtb[(size_t)DMODEL * NROWS];   // x^T bf16
__device__ __nv_bfloat16 g_wqt[(size_t)DMODEL * DMODEL];  // Wq^T
__device__ __nv_bfloat16 g_wkt[(size_t)DMODEL * DMODEL];  // Wk^T
__device__ __nv_bfloat16 g_wvb[(size_t)DMODEL * DMODEL];  // Wv
__device__ __nv_bfloat16 g_g  [(size_t)DMODEL * DMODEL];  // G row-major
__device__ __nv_bfloat16 g_xtx[(size_t)DMODEL * DMODEL];  // x^T x
__device__ __nv_bfloat16 g_ht [(size_t)DMODEL * DMODEL];  // H^T row-major
__device__ __nv_bfloat16 g_mt [(size_t)DMODEL * DMODEL];  // M^T row-major
__device__ float g_part [(size_t)8 * DMODEL * DMODEL];    // split-K partials (main)
__device__ float g_partB[(size_t)4 * DMODEL * DMODEL];    // split-K partials (side)
__device__ float g_rowsum[NROWS];
__device__ float g_xpart[32 * DMODEL];
__device__ float g_xsum[DMODEL];
__device__ float g_colsum[DMODEL];
__device__ float g_w[DMODEL];

// ---------------------------------------------------------------------------
// helpers (baseline sm_80-level PTX only -- must compile for plain sm_103)
// ---------------------------------------------------------------------------
__device__ __forceinline__ uint32_t smem_u32(const void* p) {
    uint32_t a;
    asm("{ .reg .u64 t; cvta.to.shared.u64 t, %1; cvt.u32.u64 %0, t; }"
        : "=r"(a) : "l"(p));
    return a;
}
__device__ __forceinline__ void ldsm4(uint32_t* r, uint32_t addr) {
    asm volatile("ldmatrix.sync.aligned.m8n8.x4.shared.b16 {%0,%1,%2,%3}, [%4];"
                 : "=r"(r[0]), "=r"(r[1]), "=r"(r[2]), "=r"(r[3]) : "r"(addr));
}
__device__ __forceinline__ void mma_bf16(float* d, const uint32_t* a,
                                         const uint32_t* b) {
    asm volatile(
        "mma.sync.aligned.m16n8k16.row.col.f32.bf16.bf16.f32 "
        "{%0,%1,%2,%3}, {%4,%5,%6,%7}, {%8,%9}, {%0,%1,%2,%3};"
        : "+f"(d[0]), "+f"(d[1]), "+f"(d[2]), "+f"(d[3])
        : "r"(a[0]), "r"(a[1]), "r"(a[2]), "r"(a[3]), "r"(b[0]), "r"(b[1]));
}
__device__ __forceinline__ void cp16(uint32_t d, const void* s) {
    asm volatile("cp.async.cg.shared.global [%0], [%1], 16;"
                 :: "r"(d), "l"(s) : "memory");
}
#define CP_COMMIT() asm volatile("cp.async.commit_group;" ::: "memory")
#define CP_WAIT1()  asm volatile("cp.async.wait_group 1;" ::: "memory")
#define SWZ(o) ((o) ^ (((o) >> 3) & 0x70))

__device__ __forceinline__ uint32_t pack_bf16x2(float lo, float hi) {
    uint32_t r;
    asm("cvt.rn.bf16x2.f32 %0, %1, %2;" : "=r"(r) : "f"(hi), "f"(lo));
    return r;
}

// ---------------------------------------------------------------------------
// 128x128-tile bf16 NT GEMM: C = alpha * A[*,K_full] * B[*,K_full]^T
// (both K-major, leading dim = lda). CTA computes depth slice z=blockIdx.z.
// 8 warps (2Mx4N), warp tile 64x32, BK=64, 3-stage cp.async (96 KB),
// __launch_bounds__(256,2) -> 2 CTAs/SM.
// MODE 2: C fp32 + linearized-softmax epilogue (grid.z==1).
// MODE 4: C fp32 raw partials at Cv + z*DMODEL*DMODEL (1024x1024 outputs).
// ---------------------------------------------------------------------------
#define G128_STAGE 32768
#define G128_SMEM (3 * G128_STAGE)   // 98304

template <int MODE>
__global__ __launch_bounds__(256, 2)
void gemm128(const __nv_bfloat16* __restrict__ A,
             const __nv_bfloat16* __restrict__ B,
             void* __restrict__ Cv, int N, int K, int lda, float alpha)
{
    extern __shared__ char smem[];
    const uint32_t sb = smem_u32(smem);
    const int tid = threadIdx.x, lane = tid & 31, wid = tid >> 5;
    const int wm = wid >> 2, wn = wid & 3;
    const int m0 = blockIdx.y * 128, n0 = blockIdx.x * 128;
    const size_t zoff = (size_t)blockIdx.z * K;

    const int lrow = tid >> 3;          // 0..31
    const int lseg = (tid & 7) * 16;
    const char* Ag = (const char*)A + ((size_t)(m0 + lrow) * lda + zoff) * 2 + lseg;
    const char* Bg = (const char*)B + ((size_t)(n0 + lrow) * lda + zoff) * 2 + lseg;
    const size_t rstep = (size_t)32 * lda * 2;
    uint32_t soff[4];
    #pragma unroll
    for (int i = 0; i < 4; i++)
        soff[i] = SWZ((uint32_t)((lrow + 32 * i) * 128 + lseg));

    const int nch = K / 64;
    #pragma unroll
    for (int s = 0; s < 2; s++) {
        const uint32_t st = sb + s * G128_STAGE;
        #pragma unroll
        for (int i = 0; i < 4; i++) cp16(st + soff[i],          Ag + (size_t)s * 128 + i * rstep);
        #pragma unroll
        for (int i = 0; i < 4; i++) cp16(st + 16384u + soff[i], Bg + (size_t)s * 128 + i * rstep);
        CP_COMMIT();
    }

    float acc[4][4][4] = {};
    const int a_r  = wm * 64 + (lane & 15);
    const int a_kb = ((lane >> 4) & 1) * 16;
    const int b_r  = wn * 32 + ((lane >> 4) & 1) * 8 + (lane & 7);
    const int b_kb = ((lane >> 3) & 1) * 16;

    for (int c = 0; c < nch; c++) {
        CP_WAIT1();
        __syncthreads();
        if (c + 2 < nch) {
            const uint32_t st = sb + ((c + 2) % 3) * G128_STAGE;
            #pragma unroll
            for (int i = 0; i < 4; i++)
                cp16(st + soff[i],          Ag + (size_t)(c + 2) * 128 + i * rstep);
            #pragma unroll
            for (int i = 0; i < 4; i++)
                cp16(st + 16384u + soff[i], Bg + (size_t)(c + 2) * 128 + i * rstep);
        }
        CP_COMMIT();

        const uint32_t Ab = sb + (c % 3) * G128_STAGE;
        const uint32_t Bb = Ab + 16384;
        #pragma unroll
        for (int ks = 0; ks < 4; ks++) {
            uint32_t ah[4][4], bh[2][4];
            #pragma unroll
            for (int mt = 0; mt < 4; mt++)
                ldsm4(ah[mt], Ab + SWZ((uint32_t)((a_r + mt * 16) * 128 + ks * 32 + a_kb)));
            #pragma unroll
            for (int np = 0; np < 2; np++)
                ldsm4(bh[np], Bb + SWZ((uint32_t)((b_r + np * 16) * 128 + ks * 32 + b_kb)));
            #pragma unroll
            for (int mt = 0; mt < 4; mt++)
                #pragma unroll
                for (int nt = 0; nt < 4; nt++)
                    mma_bf16(acc[mt][nt], ah[mt], &bh[nt >> 1][(nt & 1) * 2]);
        }
    }

    // ------------------------------ epilogue ------------------------------
    if (MODE == 2) {
        float* C = (float*)Cv;
        #pragma unroll
        for (int mt = 0; mt < 4; mt++) {
            const int r0 = m0 + wm * 64 + mt * 16 + (lane >> 2);
            const float c0 = 1.f / (8192.f + g_rowsum[r0]);
            const float c1 = 1.f / (8192.f + g_rowsum[r0 + 8]);
            #pragma unroll
            for (int nt = 0; nt < 4; nt++) {
                const int col = n0 + wn * 32 + nt * 8 + (lane & 3) * 2;
                const float2 cs = *(const float2*)&g_colsum[col];
                float2 o0, o1;
                o0.x = c0 * (acc[mt][nt][0] * alpha + cs.x);
                o0.y = c0 * (acc[mt][nt][1] * alpha + cs.y);
                o1.x = c1 * (acc[mt][nt][2] * alpha + cs.x);
                o1.y = c1 * (acc[mt][nt][3] * alpha + cs.y);
                *(float2*)(C + (size_t)r0 * N + col)       = o0;
                *(float2*)(C + (size_t)(r0 + 8) * N + col) = o1;
            }
        }
    }
    if (MODE == 4) {
        float* C = (float*)Cv + (size_t)blockIdx.z * DMODEL * DMODEL;
        #pragma unroll
        for (int mt = 0; mt < 4; mt++) {
            const int r0 = m0 + wm * 64 + mt * 16 + (lane >> 2);
            #pragma unroll
            for (int nt = 0; nt < 4; nt++) {
                const int col = n0 + wn * 32 + nt * 8 + (lane & 3) * 2;
                *(float2*)(C + (size_t)r0 * N + col) =
                    make_float2(acc[mt][nt][0], acc[mt][nt][1]);
                *(float2*)(C + (size_t)(r0 + 8) * N + col) =
                    make_float2(acc[mt][nt][2], acc[mt][nt][3]);
            }
        }
    }
}

// ---------------------------------------------------------------------------
// SYRK kernel for xtx: same geometry, lower-triangle tiles only (y >= x),
// split-K z=4 -> 144 CTAs. Writes fp32 partials.
// ---------------------------------------------------------------------------
__global__ __launch_bounds__(256, 2)
void gemm_syrk128(const __nv_bfloat16* __restrict__ A,
                  float* __restrict__ part, int K)
{
    if ((int)blockIdx.y < (int)blockIdx.x) return;

    extern __shared__ char smem[];
    const uint32_t sb = smem_u32(smem);
    const int tid = threadIdx.x, lane = tid & 31, wid = tid >> 5;
    const int wm = wid >> 2, wn = wid & 3;
    const int m0 = blockIdx.y * 128, n0 = blockIdx.x * 128;
    const size_t zoff = (size_t)blockIdx.z * K;
    const int lda = NROWS;

    const int lrow = tid >> 3;
    const int lseg = (tid & 7) * 16;
    const char* Ag = (const char*)A + ((size_t)(m0 + lrow) * lda + zoff) * 2 + lseg;
    const char* Bg = (const char*)A + ((size_t)(n0 + lrow) * lda + zoff) * 2 + lseg;
    const size_t rstep = (size_t)32 * lda * 2;
    uint32_t soff[4];
    #pragma unroll
    for (int i = 0; i < 4; i++)
        soff[i] = SWZ((uint32_t)((lrow + 32 * i) * 128 + lseg));

    const int nch = K / 64;
    #pragma unroll
    for (int s = 0; s < 2; s++) {
        const uint32_t st = sb + s * G128_STAGE;
        #pragma unroll
        for (int i = 0; i < 4; i++) cp16(st + soff[i],          Ag + (size_t)s * 128 + i * rstep);
        #pragma unroll
        for (int i = 0; i < 4; i++) cp16(st + 16384u + soff[i], Bg + (size_t)s * 128 + i * rstep);
        CP_COMMIT();
    }

    float acc[4][4][4] = {};
    const int a_r  = wm * 64 + (lane & 15);
    const int a_kb = ((lane >> 4) & 1) * 16;
    const int b_r  = wn * 32 + ((lane >> 4) & 1) * 8 + (lane & 7);
    const int b_kb = ((lane >> 3) & 1) * 16;

    for (int c = 0; c < nch; c++) {
        CP_WAIT1();
        __syncthreads();
        if (c + 2 < nch) {
            const uint32_t st = sb + ((c + 2) % 3) * G128_STAGE;
            #pragma unroll
            for (int i = 0; i < 4; i++)
                cp16(st + soff[i],          Ag + (size_t)(c + 2) * 128 + i * rstep);
            #pragma unroll
            for (int i = 0; i < 4; i++)
                cp16(st + 16384u + soff[i], Bg + (size_t)(c + 2) * 128 + i * rstep);
        }
        CP_COMMIT();

        const uint32_t Ab = sb + (c % 3) * G128_STAGE;
        const uint32_t Bb = Ab + 16384;
        #pragma unroll
        for (int ks = 0; ks < 4; ks++) {
            uint32_t ah[4][4], bh[2][4];
            #pragma unroll
            for (int mt = 0; mt < 4; mt++)
                ldsm4(ah[mt], Ab + SWZ((uint32_t)((a_r + mt * 16) * 128 + ks * 32 + a_kb)));
            #pragma unroll
            for (int np = 0; np < 2; np++)
                ldsm4(bh[np], Bb + SWZ((uint32_t)((b_r + np * 16) * 128 + ks * 32 + b_kb)));
            #pragma unroll
            for (int mt = 0; mt < 4; mt++)
                #pragma unroll
                for (int nt = 0; nt < 4; nt++)
                    mma_bf16(acc[mt][nt], ah[mt], &bh[nt >> 1][(nt & 1) * 2]);
        }
    }

    float* P = part + (size_t)blockIdx.z * DMODEL * DMODEL;
    #pragma unroll
    for (int mt = 0; mt < 4; mt++) {
        const int r0 = m0 + wm * 64 + mt * 16 + (lane >> 2);
        #pragma unroll
        for (int nt = 0; nt < 4; nt++) {
            const int col = n0 + wn * 32 + nt * 8 + (lane & 3) * 2;
            *(float2*)(P + (size_t)r0 * DMODEL + col) =
                make_float2(acc[mt][nt][0], acc[mt][nt][1]);
            *(float2*)(P + (size_t)(r0 + 8) * DMODEL + col) =
                make_float2(acc[mt][nt][2], acc[mt][nt][3]);
        }
    }
}

// ---------------------------------------------------------------------------
// small kernels
// ---------------------------------------------------------------------------
// fused: xb = bf16(x) and per-256-row column partial sums. grid (4,32), blk 256
__global__ void cvt_x_sum(const float* __restrict__ x,
                          __nv_bfloat16* __restrict__ xb)
{
    const int col = blockIdx.x * 256 + threadIdx.x;
    const int r0  = blockIdx.y * 256;
    float s = 0.f;
    #pragma unroll 4
    for (int j = 0; j < 256; j++) {
        float f = x[(size_t)(r0 + j) * DMODEL + col];
        s += f;
        xb[(size_t)(r0 + j) * DMODEL + col] = __float2bfloat16(f);
    }
    g_xpart[blockIdx.y * DMODEL + col] = s;
}

__global__ void cvt_f32_bf16(const float* __restrict__ src,
                             __nv_bfloat16* __restrict__ dst, int n4)
{
    int i = blockIdx.x * blockDim.x + threadIdx.x;
    if (i < n4) {
        float4 f = ((const float4*)src)[i];
        uint2 o;
        o.x = pack_bf16x2(f.x, f.y);
        o.y = pack_bf16x2(f.z, f.w);
        ((uint2*)dst)[i] = o;
    }
}

// transpose-convert: dst[c,r] = bf16(src[r,c]); src [R,C] fp32. grid (C/32,R/32)
__global__ void cvt_transpose(const float* __restrict__ src,
                              __nv_bfloat16* __restrict__ dst, int R, int C)
{
    __shared__ float tile[32][33];
    const int x0 = blockIdx.x * 32, y0 = blockIdx.y * 32;
    #pragma unroll
    for (int i = 0; i < 4; i++)
        tile[threadIdx.y + i * 8][threadIdx.x] =
            src[(size_t)(y0 + threadIdx.y + i * 8) * C + x0 + threadIdx.x];
    __syncthreads();
    #pragma unroll
    for (int i = 0; i < 4; i++)
        dst[(size_t)(x0 + threadIdx.y + i * 8) * R + y0 + threadIdx.x] =
            __float2bfloat16(tile[threadIdx.x][threadIdx.y + i * 8]);
}

// fused reduce (z=4 split-K partials) + mirror for xtx.
// SYRK computed only 128-tiles with (m>>7) >= (n>>7). For each 32x32 block in
// that region: reduce partials -> bf16, write direct; if strictly lower
// (m>>7) > (n>>7), also write the transposed block (its mirror target is in
// the skipped upper region, written by no one else). grid (32,32), blk (32,8).
__global__ void reduce_mirror_xtx(const float* __restrict__ part,
                                  __nv_bfloat16* __restrict__ xtx)
{
    const int m0 = blockIdx.y * 32, n0 = blockIdx.x * 32;
    if ((m0 >> 7) < (n0 >> 7)) return;   // upper region: filled by mirror
    __shared__ __nv_bfloat16 t[32][33];
    const int tx = threadIdx.x, ty = threadIdx.y;
    #pragma unroll
    for (int i = 0; i < 4; i++) {
        const int row = m0 + ty + i * 8;
        const size_t idx = (size_t)row * DMODEL + n0 + tx;
        float s = part[idx] + part[idx + (size_t)DMODEL * DMODEL]
                + part[idx + 2 * (size_t)DMODEL * DMODEL]
                + part[idx + 3 * (size_t)DMODEL * DMODEL];
        __nv_bfloat16 v = __float2bfloat16(s);
        xtx[idx] = v;
        t[ty + i * 8][tx] = v;
    }
    if ((m0 >> 7) > (n0 >> 7)) {
        __syncthreads();
        #pragma unroll
        for (int i = 0; i < 4; i++)
            xtx[(size_t)(n0 + ty + i * 8) * DMODEL + m0 + tx] = t[tx][ty + i * 8];
    }
}

// reduce split-K fp32 partials -> bf16
__global__ void reduce_partials(const float* __restrict__ part,
                                __nv_bfloat16* __restrict__ dst, int n, int z)
{
    int i = blockIdx.x * 256 + threadIdx.x;
    if (i < n) {
        float s = 0.f;
        for (int zz = 0; zz < z; zz++) s += part[(size_t)zz * n + i];
        dst[i] = __float2bfloat16(s);
    }
}

__global__ void reduce_xsum()
{
    const int i = blockIdx.x * 256 + threadIdx.x;   // grid 4
    float s = 0.f;
    #pragma unroll
    for (int p = 0; p < 32; p++) s += g_xpart[p * DMODEL + i];
    g_xsum[i] = s;
}

// colsum_d = Wv[d,:] . xsum  (exact fp32); grid 1024, block 128
__global__ void colvec_kernel(const float* __restrict__ Wv)
{
    __shared__ float red[128];
    const int d = blockIdx.x;
    float s = 0.f;
    for (int i = threadIdx.x; i < DMODEL; i += 128)
        s += Wv[(size_t)d * DMODEL + i] * g_xsum[i];
    red[threadIdx.x] = s;
    __syncthreads();
    for (int st = 64; st > 0; st >>= 1) {
        if (threadIdx.x < st) red[threadIdx.x] += red[threadIdx.x + st];
        __syncthreads();
    }
    if (threadIdx.x == 0) g_colsum[d] = red[0];
}

// w[k] = G[k,:] . xsum ; grid 1024, block 128 (G bf16 row-major)
__global__ void wvec_kernel(const __nv_bfloat16* __restrict__ G)
{
    __shared__ float red[128];
    const int k = blockIdx.x;
    float s = 0.f;
    for (int i = threadIdx.x; i < DMODEL; i += 128)
        s += __bfloat162float(G[(size_t)k * DMODEL + i]) * g_xsum[i];
    red[threadIdx.x] = s;
    __syncthreads();
    for (int st = 64; st > 0; st >>= 1) {
        if (threadIdx.x < st) red[threadIdx.x] += red[threadIdx.x + st];
        __syncthreads();
    }
    if (threadIdx.x == 0) g_w[k] = red[0];
}

// rowsum_r = (x_r . w) / 8192 ; one warp per row, 8 rows per block
__global__ void rowsum_kernel(const __nv_bfloat16* __restrict__ xb)
{
    const int row  = blockIdx.x * 8 + (threadIdx.x >> 5);
    const int lane = threadIdx.x & 31;
    const uint2* p = (const uint2*)(xb + (size_t)row * DMODEL);
    float s = 0.f;
    #pragma unroll
    for (int j = lane; j < 256; j += 32) {          // uint2 = 4 bf16
        uint2 u = p[j];
        float4 ws = ((const float4*)g_w)[j];
        s += __uint_as_float(u.x << 16) * ws.x;
        s += __uint_as_float(u.x & 0xFFFF0000u) * ws.y;
        s += __uint_as_float(u.y << 16) * ws.z;
        s += __uint_as_float(u.y & 0xFFFF0000u) * ws.w;
    }
    #pragma unroll
    for (int o = 16; o > 0; o >>= 1) s += __shfl_xor_sync(~0u, s, o);
    if (lane == 0) g_rowsum[row] = s * (1.f / 8192.f);
}

// ---------------------------------------------------------------------------
// launch: fork-join two-stream graph
// ---------------------------------------------------------------------------
extern "C" void kernel_launch(void* const* d_in, const int* in_sizes, int n_in,
                              void* d_out, int out_size)
{
    const float* x  = (const float*)d_in[0];
    const float* Wq = (const float*)d_in[1];
    const float* Wk = (const float*)d_in[2];
    const float* Wv = (const float*)d_in[3];
    float* out = (float*)d_out;

    __nv_bfloat16 *xb, *xtb, *wqt, *wkt, *wvb, *gg, *xtx, *ht, *mt;
    float *part, *partB;
    cudaGetSymbolAddress((void**)&xb,    g_xb);
    cudaGetSymbolAddress((void**)&xtb,   g_xtb);
    cudaGetSymbolAddress((void**)&wqt,   g_wqt);
    cudaGetSymbolAddress((void**)&wkt,   g_wkt);
    cudaGetSymbolAddress((void**)&wvb,   g_wvb);
    cudaGetSymbolAddress((void**)&gg,    g_g);
    cudaGetSymbolAddress((void**)&xtx,   g_xtx);
    cudaGetSymbolAddress((void**)&ht,    g_ht);
    cudaGetSymbolAddress((void**)&mt,    g_mt);
    cudaGetSymbolAddress((void**)&part,  g_part);
    cudaGetSymbolAddress((void**)&partB, g_partB);

    static bool init_done = false;
    static cudaStream_t s1;
    static cudaEvent_t evFork, evWvb, evG, evSide;
    if (!init_done) {
        cudaFuncSetAttribute(gemm128<2>, cudaFuncAttributeMaxDynamicSharedMemorySize, G128_SMEM);
        cudaFuncSetAttribute(gemm128<4>, cudaFuncAttributeMaxDynamicSharedMemorySize, G128_SMEM);
        cudaFuncSetAttribute(gemm_syrk128, cudaFuncAttributeMaxDynamicSharedMemorySize, G128_SMEM);
        cudaStreamCreateWithFlags(&s1, cudaStreamNonBlocking);
        cudaEventCreateWithFlags(&evFork, cudaEventDisableTiming);
        cudaEventCreateWithFlags(&evWvb,  cudaEventDisableTiming);
        cudaEventCreateWithFlags(&evG,    cudaEventDisableTiming);
        cudaEventCreateWithFlags(&evSide, cudaEventDisableTiming);
        init_done = true;
    }

    const dim3 blk(256);

    // ---- fork ----
    cudaEventRecord(evFork, 0);
    cudaStreamWaitEvent(s1, evFork, 0);

    // ======================= side stream (s1) =======================
    cvt_f32_bf16<<<DMODEL * DMODEL / 4 / 256, 256, 0, s1>>>(Wv, wvb, DMODEL * DMODEL / 4);
    cudaEventRecord(evWvb, s1);
    cvt_x_sum<<<dim3(4, 32), 256, 0, s1>>>(x, xb);
    cvt_transpose<<<dim3(32, 32), dim3(32, 8), 0, s1>>>(Wq, wqt, DMODEL, DMODEL);
    cvt_transpose<<<dim3(32, 32), dim3(32, 8), 0, s1>>>(Wk, wkt, DMODEL, DMODEL);
    // G = NT(wqt, wkt): G[k,j] = sum_d Wq[d,k] Wk[d,j], split-K 4 (partB)
    gemm128<4><<<dim3(8, 8, 4), blk, G128_SMEM, s1>>>(
        wqt, wkt, partB, DMODEL, 256, DMODEL, 1.0f);
    reduce_partials<<<4096, 256, 0, s1>>>(partB, gg, DMODEL * DMODEL, 4);
    cudaEventRecord(evG, s1);
    reduce_xsum<<<4, 256, 0, s1>>>();
    colvec_kernel<<<1024, 128, 0, s1>>>(Wv);
    wvec_kernel<<<1024, 128, 0, s1>>>(gg);
    rowsum_kernel<<<NROWS / 8, 256, 0, s1>>>(xb);
    cudaEventRecord(evSide, s1);

    // ======================= main stream (critical path) =======================
    cvt_transpose<<<dim3(DMODEL / 32, NROWS / 32), dim3(32, 8)>>>(x, xtb, NROWS, DMODEL);
    // xtx = NT(xtb, xtb): 128x128 SYRK tiles (y>=x), z=4 -> 144 CTAs
    gemm_syrk128<<<dim3(8, 8, 4), blk, G128_SMEM>>>(xtb, part, NROWS / 4);
    // fused reduce + mirror
    reduce_mirror_xtx<<<dim3(32, 32), dim3(32, 8)>>>(part, xtx);
    // Ht = NT(wvb, xtx): ht[d,i] = (Wv x^T x)[d,i] = H[i,d]
    cudaStreamWaitEvent(0, evWvb, 0);
    gemm128<4><<<dim3(8, 8, 4), blk, G128_SMEM>>>(
        wvb, xtx, part, DMODEL, 256, DMODEL, 1.0f);
    reduce_partials<<<4096, 256>>>(part, ht, DMODEL * DMODEL, 4);
    // Mt = NT(ht, gg): mt[d,k] = sum_i H[i,d] G[k,i] = (G H)[k,d] = M^T
    cudaStreamWaitEvent(0, evG, 0);
    gemm128<4><<<dim3(8, 8, 4), blk, G128_SMEM>>>(
        ht, gg, part, DMODEL, 256, DMODEL, 1.0f);
    reduce_partials<<<4096, 256>>>(part, mt, DMODEL * DMODEL, 4);
    // join side stream, then final GEMM with affine epilogue
    cudaStreamWaitEvent(0, evSide, 0);
    gemm128<2><<<dim3(8, 64, 1), blk, G128_SMEM>>>(
        xb, mt, out, DMODEL, DMODEL, DMODEL, 1.0f / 8192.0f);
}

// round 16
// speedup vs baseline: 1.0678x; 1.0678x over previous
#include <cuda_runtime.h>
#include <cuda_bf16.h>
#include <cstdint>
#include <cstddef>

// ============================================================================
// ClassicalAttentionLayer, round 16: R14 configuration (best verified:
// 128x256 tiles for G/Ht/Mt/final at occ 1; 128x128 single-wave SYRK for
// x^T x) + R15's fused reduce+mirror for xtx.
//   out[r,d] = (colsum_d + (x @ M)[r,d]/8192) / (8192 + rowsum_r)
//   M = G H,  G = Wq^T Wk,  H = (x^T x) Wv^T
//   rowsum_r = x_r . w / 8192,  w = G xsum
//   colsum = Wv @ xsum (exact fp32), xsum = column sums of x (exact fp32)
// Critical path (stream 0): cvt_transpose(x) -> xtx(syrk128) ->
// reduce+mirror -> Ht -> reduce -> Mt -> reduce -> final.
// Side: conversions, stats, G.
// ============================================================================

#define NROWS 8192
#define DMODEL 1024

__device__ __nv_bfloat16 g_xb [(size_t)NROWS * DMODEL];   // x bf16 row-major
__device__ __nv_bfloat16 g_xtb[(size_t)DMODEL * NROWS];   // x^T bf16
__device__ __nv_bfloat16 g_wqt[(size_t)DMODEL * DMODEL];  // Wq^T
__device__ __nv_bfloat16 g_wkt[(size_t)DMODEL * DMODEL];  // Wk^T
__device__ __nv_bfloat16 g_wvb[(size_t)DMODEL * DMODEL];  // Wv
__device__ __nv_bfloat16 g_g  [(size_t)DMODEL * DMODEL];  // G row-major
__device__ __nv_bfloat16 g_xtx[(size_t)DMODEL * DMODEL];  // x^T x
__device__ __nv_bfloat16 g_ht [(size_t)DMODEL * DMODEL];  // H^T row-major
__device__ __nv_bfloat16 g_mt [(size_t)DMODEL * DMODEL];  // M^T row-major
__device__ float g_part [(size_t)8 * DMODEL * DMODEL];    // split-K partials (main)
__device__ float g_partB[(size_t)4 * DMODEL * DMODEL];    // split-K partials (side)
__device__ float g_rowsum[NROWS];
__device__ float g_xpart[32 * DMODEL];
__device__ float g_xsum[DMODEL];
__device__ float g_colsum[DMODEL];
__device__ float g_w[DMODEL];

// ---------------------------------------------------------------------------
// helpers (baseline sm_80-level PTX only -- must compile for plain sm_103)
// ---------------------------------------------------------------------------
__device__ __forceinline__ uint32_t smem_u32(const void* p) {
    uint32_t a;
    asm("{ .reg .u64 t; cvta.to.shared.u64 t, %1; cvt.u32.u64 %0, t; }"
        : "=r"(a) : "l"(p));
    return a;
}
__device__ __forceinline__ void ldsm4(uint32_t* r, uint32_t addr) {
    asm volatile("ldmatrix.sync.aligned.m8n8.x4.shared.b16 {%0,%1,%2,%3}, [%4];"
                 : "=r"(r[0]), "=r"(r[1]), "=r"(r[2]), "=r"(r[3]) : "r"(addr));
}
__device__ __forceinline__ void mma_bf16(float* d, const uint32_t* a,
                                         const uint32_t* b) {
    asm volatile(
        "mma.sync.aligned.m16n8k16.row.col.f32.bf16.bf16.f32 "
        "{%0,%1,%2,%3}, {%4,%5,%6,%7}, {%8,%9}, {%0,%1,%2,%3};"
        : "+f"(d[0]), "+f"(d[1]), "+f"(d[2]), "+f"(d[3])
        : "r"(a[0]), "r"(a[1]), "r"(a[2]), "r"(a[3]), "r"(b[0]), "r"(b[1]));
}
__device__ __forceinline__ void cp16(uint32_t d, const void* s) {
    asm volatile("cp.async.cg.shared.global [%0], [%1], 16;"
                 :: "r"(d), "l"(s) : "memory");
}
#define CP_COMMIT() asm volatile("cp.async.commit_group;" ::: "memory")
#define CP_WAIT1()  asm volatile("cp.async.wait_group 1;" ::: "memory")
#define SWZ(o) ((o) ^ (((o) >> 3) & 0x70))

__device__ __forceinline__ uint32_t pack_bf16x2(float lo, float hi) {
    uint32_t r;
    asm("cvt.rn.bf16x2.f32 %0, %1, %2;" : "=r"(r) : "f"(hi), "f"(lo));
    return r;
}

// ---------------------------------------------------------------------------
// bf16 NT GEMM: C = alpha * A[M,K_full] * B[N,K_full]^T (K-major, lda=K_full)
// CTA computes depth slice [z*K,(z+1)*K), z=blockIdx.z.
// CTA tile 128x256, BK=64, 3-stage cp.async, 8 warps, warp tile 64x64.
// MODE 2: C fp32 + linearized-softmax epilogue (grid.z==1).
// MODE 4: C fp32 raw partials at Cv + z*M*N.
// ---------------------------------------------------------------------------
#define STAGE_BYTES 49152
#define SMEM_TOTAL (3 * STAGE_BYTES)

template <int MODE>
__global__ __launch_bounds__(256, 1)
void gemm_nt(const __nv_bfloat16* __restrict__ A,
             const __nv_bfloat16* __restrict__ B,
             void* __restrict__ Cv, int M, int N, int K, int lda, float alpha)
{
    extern __shared__ char smem[];
    const uint32_t sb = smem_u32(smem);
    const int tid = threadIdx.x, lane = tid & 31, wid = tid >> 5;
    const int wm = wid >> 2, wn = wid & 3;
    const int m0 = blockIdx.y * 128, n0 = blockIdx.x * 256;
    const size_t zoff = (size_t)blockIdx.z * K;

    const int lrow = tid >> 3;
    const int lseg = (tid & 7) * 16;
    const char* Ag = (const char*)A + ((size_t)(m0 + lrow) * lda + zoff) * 2 + lseg;
    const char* Bg = (const char*)B + ((size_t)(n0 + lrow) * lda + zoff) * 2 + lseg;
    const size_t rstep = (size_t)32 * lda * 2;
    uint32_t soffA[4], soffB[8];
    #pragma unroll
    for (int i = 0; i < 4; i++)
        soffA[i] = SWZ((uint32_t)((lrow + 32 * i) * 128 + lseg));
    #pragma unroll
    for (int i = 0; i < 8; i++)
        soffB[i] = 16384u + SWZ((uint32_t)((lrow + 32 * i) * 128 + lseg));

    const int nch = K / 64;
    #pragma unroll
    for (int s = 0; s < 2; s++) {
        const uint32_t st = sb + s * STAGE_BYTES;
        #pragma unroll
        for (int i = 0; i < 4; i++) cp16(st + soffA[i], Ag + (size_t)s * 128 + i * rstep);
        #pragma unroll
        for (int i = 0; i < 8; i++) cp16(st + soffB[i], Bg + (size_t)s * 128 + i * rstep);
        CP_COMMIT();
    }

    float acc[4][8][4] = {};
    const int a_r  = wm * 64 + (lane & 15);
    const int a_kb = ((lane >> 4) & 1) * 16;
    const int b_r  = wn * 64 + ((lane >> 4) & 1) * 8 + (lane & 7);
    const int b_kb = ((lane >> 3) & 1) * 16;

    for (int c = 0; c < nch; c++) {
        CP_WAIT1();
        __syncthreads();
        if (c + 2 < nch) {
            const uint32_t st = sb + ((c + 2) % 3) * STAGE_BYTES;
            #pragma unroll
            for (int i = 0; i < 4; i++)
                cp16(st + soffA[i], Ag + (size_t)(c + 2) * 128 + i * rstep);
            #pragma unroll
            for (int i = 0; i < 8; i++)
                cp16(st + soffB[i], Bg + (size_t)(c + 2) * 128 + i * rstep);
        }
        CP_COMMIT();

        const uint32_t Ab = sb + (c % 3) * STAGE_BYTES;
        const uint32_t Bb = Ab + 16384;
        #pragma unroll
        for (int ks = 0; ks < 4; ks++) {
            uint32_t ah[4][4], bh[4][4];
            #pragma unroll
            for (int mt = 0; mt < 4; mt++)
                ldsm4(ah[mt], Ab + SWZ((uint32_t)((a_r + mt * 16) * 128 + ks * 32 + a_kb)));
            #pragma unroll
            for (int np = 0; np < 4; np++)
                ldsm4(bh[np], Bb + SWZ((uint32_t)((b_r + np * 16) * 128 + ks * 32 + b_kb)));
            #pragma unroll
            for (int mt = 0; mt < 4; mt++)
                #pragma unroll
                for (int nt = 0; nt < 8; nt++)
                    mma_bf16(acc[mt][nt], ah[mt], &bh[nt >> 1][(nt & 1) * 2]);
        }
    }

    // ------------------------------ epilogue ------------------------------
    if (MODE == 2) {
        float* C = (float*)Cv;
        #pragma unroll
        for (int mt = 0; mt < 4; mt++) {
            const int r0 = m0 + wm * 64 + mt * 16 + (lane >> 2);
            const float c0 = 1.f / (8192.f + g_rowsum[r0]);
            const float c1 = 1.f / (8192.f + g_rowsum[r0 + 8]);
            #pragma unroll
            for (int nt = 0; nt < 8; nt++) {
                const int col = n0 + wn * 64 + nt * 8 + (lane & 3) * 2;
                const float2 cs = *(const float2*)&g_colsum[col];
                float2 o0, o1;
                o0.x = c0 * (acc[mt][nt][0] * alpha + cs.x);
                o0.y = c0 * (acc[mt][nt][1] * alpha + cs.y);
                o1.x = c1 * (acc[mt][nt][2] * alpha + cs.x);
                o1.y = c1 * (acc[mt][nt][3] * alpha + cs.y);
                *(float2*)(C + (size_t)r0 * N + col)       = o0;
                *(float2*)(C + (size_t)(r0 + 8) * N + col) = o1;
            }
        }
    }
    if (MODE == 4) {
        float* C = (float*)Cv + (size_t)blockIdx.z * M * N;
        #pragma unroll
        for (int mt = 0; mt < 4; mt++) {
            const int r0 = m0 + wm * 64 + mt * 16 + (lane >> 2);
            #pragma unroll
            for (int nt = 0; nt < 8; nt++) {
                const int col = n0 + wn * 64 + nt * 8 + (lane & 3) * 2;
                *(float2*)(C + (size_t)r0 * N + col) =
                    make_float2(acc[mt][nt][0], acc[mt][nt][1]);
                *(float2*)(C + (size_t)(r0 + 8) * N + col) =
                    make_float2(acc[mt][nt][2], acc[mt][nt][3]);
            }
        }
    }
}

// ---------------------------------------------------------------------------
// SYRK kernel for xtx: 128x128 CTA tile, lower-triangle tiles only
// (blockIdx.y >= blockIdx.x), split-K via blockIdx.z (z=4, K=2048/slice).
// 8 warps (2x4), warp tile 64x32, BK=64, 3-stage cp.async (96 KB smem).
// Writes fp32 partials to part + z*DMODEL*DMODEL.
// ---------------------------------------------------------------------------
#define SYRK_STAGE 32768
#define SYRK_SMEM (3 * SYRK_STAGE)   // 98304

__global__ __launch_bounds__(256, 1)
void gemm_syrk128(const __nv_bfloat16* __restrict__ A,
                  float* __restrict__ part, int K)
{
    if ((int)blockIdx.y < (int)blockIdx.x) return;   // upper tiles mirrored later

    extern __shared__ char smem[];
    const uint32_t sb = smem_u32(smem);
    const int tid = threadIdx.x, lane = tid & 31, wid = tid >> 5;
    const int wm = wid >> 2, wn = wid & 3;
    const int m0 = blockIdx.y * 128, n0 = blockIdx.x * 128;
    const size_t zoff = (size_t)blockIdx.z * K;
    const int lda = NROWS;

    const int lrow = tid >> 3;
    const int lseg = (tid & 7) * 16;
    const char* Ag = (const char*)A + ((size_t)(m0 + lrow) * lda + zoff) * 2 + lseg;
    const char* Bg = (const char*)A + ((size_t)(n0 + lrow) * lda + zoff) * 2 + lseg;
    const size_t rstep = (size_t)32 * lda * 2;
    uint32_t soff[4];
    #pragma unroll
    for (int i = 0; i < 4; i++)
        soff[i] = SWZ((uint32_t)((lrow + 32 * i) * 128 + lseg));

    const int nch = K / 64;
    #pragma unroll
    for (int s = 0; s < 2; s++) {
        const uint32_t st = sb + s * SYRK_STAGE;
        #pragma unroll
        for (int i = 0; i < 4; i++) cp16(st + soff[i],          Ag + (size_t)s * 128 + i * rstep);
        #pragma unroll
        for (int i = 0; i < 4; i++) cp16(st + 16384u + soff[i], Bg + (size_t)s * 128 + i * rstep);
        CP_COMMIT();
    }

    float acc[4][4][4] = {};
    const int a_r  = wm * 64 + (lane & 15);
    const int a_kb = ((lane >> 4) & 1) * 16;
    const int b_r  = wn * 32 + ((lane >> 4) & 1) * 8 + (lane & 7);
    const int b_kb = ((lane >> 3) & 1) * 16;

    for (int c = 0; c < nch; c++) {
        CP_WAIT1();
        __syncthreads();
        if (c + 2 < nch) {
            const uint32_t st = sb + ((c + 2) % 3) * SYRK_STAGE;
            #pragma unroll
            for (int i = 0; i < 4; i++)
                cp16(st + soff[i],          Ag + (size_t)(c + 2) * 128 + i * rstep);
            #pragma unroll
            for (int i = 0; i < 4; i++)
                cp16(st + 16384u + soff[i], Bg + (size_t)(c + 2) * 128 + i * rstep);
        }
        CP_COMMIT();

        const uint32_t Ab = sb + (c % 3) * SYRK_STAGE;
        const uint32_t Bb = Ab + 16384;
        #pragma unroll
        for (int ks = 0; ks < 4; ks++) {
            uint32_t ah[4][4], bh[2][4];
            #pragma unroll
            for (int mt = 0; mt < 4; mt++)
                ldsm4(ah[mt], Ab + SWZ((uint32_t)((a_r + mt * 16) * 128 + ks * 32 + a_kb)));
            #pragma unroll
            for (int np = 0; np < 2; np++)
                ldsm4(bh[np], Bb + SWZ((uint32_t)((b_r + np * 16) * 128 + ks * 32 + b_kb)));
            #pragma unroll
            for (int mt = 0; mt < 4; mt++)
                #pragma unroll
                for (int nt = 0; nt < 4; nt++)
                    mma_bf16(acc[mt][nt], ah[mt], &bh[nt >> 1][(nt & 1) * 2]);
        }
    }

    float* P = part + (size_t)blockIdx.z * DMODEL * DMODEL;
    #pragma unroll
    for (int mt = 0; mt < 4; mt++) {
        const int r0 = m0 + wm * 64 + mt * 16 + (lane >> 2);
        #pragma unroll
        for (int nt = 0; nt < 4; nt++) {
            const int col = n0 + wn * 32 + nt * 8 + (lane & 3) * 2;
            *(float2*)(P + (size_t)r0 * DMODEL + col) =
                make_float2(acc[mt][nt][0], acc[mt][nt][1]);
            *(float2*)(P + (size_t)(r0 + 8) * DMODEL + col) =
                make_float2(acc[mt][nt][2], acc[mt][nt][3]);
        }
    }
}

// ---------------------------------------------------------------------------
// small kernels
// ---------------------------------------------------------------------------
// fused: xb = bf16(x) and per-256-row column partial sums. grid (4,32), blk 256
__global__ void cvt_x_sum(const float* __restrict__ x,
                          __nv_bfloat16* __restrict__ xb)
{
    const int col = blockIdx.x * 256 + threadIdx.x;
    const int r0  = blockIdx.y * 256;
    float s = 0.f;
    #pragma unroll 4
    for (int j = 0; j < 256; j++) {
        float f = x[(size_t)(r0 + j) * DMODEL + col];
        s += f;
        xb[(size_t)(r0 + j) * DMODEL + col] = __float2bfloat16(f);
    }
    g_xpart[blockIdx.y * DMODEL + col] = s;
}

__global__ void cvt_f32_bf16(const float* __restrict__ src,
                             __nv_bfloat16* __restrict__ dst, int n4)
{
    int i = blockIdx.x * blockDim.x + threadIdx.x;
    if (i < n4) {
        float4 f = ((const float4*)src)[i];
        uint2 o;
        o.x = pack_bf16x2(f.x, f.y);
        o.y = pack_bf16x2(f.z, f.w);
        ((uint2*)dst)[i] = o;
    }
}

// transpose-convert: dst[c,r] = bf16(src[r,c]); src [R,C] fp32. grid (C/32,R/32)
__global__ void cvt_transpose(const float* __restrict__ src,
                              __nv_bfloat16* __restrict__ dst, int R, int C)
{
    __shared__ float tile[32][33];
    const int x0 = blockIdx.x * 32, y0 = blockIdx.y * 32;
    #pragma unroll
    for (int i = 0; i < 4; i++)
        tile[threadIdx.y + i * 8][threadIdx.x] =
            src[(size_t)(y0 + threadIdx.y + i * 8) * C + x0 + threadIdx.x];
    __syncthreads();
    #pragma unroll
    for (int i = 0; i < 4; i++)
        dst[(size_t)(x0 + threadIdx.y + i * 8) * R + y0 + threadIdx.x] =
            __float2bfloat16(tile[threadIdx.x][threadIdx.y + i * 8]);
}

// fused reduce (z=4 split-K partials) + mirror for xtx.
// SYRK computed only 128-tiles with (m>>7) >= (n>>7). For each 32x32 block in
// that region: reduce partials -> bf16, write direct; if strictly lower
// (m>>7) > (n>>7), also write the transposed block. grid (32,32), blk (32,8).
__global__ void reduce_mirror_xtx(const float* __restrict__ part,
                                  __nv_bfloat16* __restrict__ xtx)
{
    const int m0 = blockIdx.y * 32, n0 = blockIdx.x * 32;
    if ((m0 >> 7) < (n0 >> 7)) return;   // upper region: filled by mirror
    __shared__ __nv_bfloat16 t[32][33];
    const int tx = threadIdx.x, ty = threadIdx.y;
    #pragma unroll
    for (int i = 0; i < 4; i++) {
        const int row = m0 + ty + i * 8;
        const size_t idx = (size_t)row * DMODEL + n0 + tx;
        float s = part[idx] + part[idx + (size_t)DMODEL * DMODEL]
                + part[idx + 2 * (size_t)DMODEL * DMODEL]
                + part[idx + 3 * (size_t)DMODEL * DMODEL];
        __nv_bfloat16 v = __float2bfloat16(s);
        xtx[idx] = v;
        t[ty + i * 8][tx] = v;
    }
    if ((m0 >> 7) > (n0 >> 7)) {
        __syncthreads();
        #pragma unroll
        for (int i = 0; i < 4; i++)
            xtx[(size_t)(n0 + ty + i * 8) * DMODEL + m0 + tx] = t[tx][ty + i * 8];
    }
}

// reduce split-K fp32 partials -> bf16
__global__ void reduce_partials(const float* __restrict__ part,
                                __nv_bfloat16* __restrict__ dst, int n, int z)
{
    int i = blockIdx.x * 256 + threadIdx.x;
    if (i < n) {
        float s = 0.f;
        for (int zz = 0; zz < z; zz++) s += part[(size_t)zz * n + i];
        dst[i] = __float2bfloat16(s);
    }
}

__global__ void reduce_xsum()
{
    const int i = blockIdx.x * 256 + threadIdx.x;   // grid 4
    float s = 0.f;
    #pragma unroll
    for (int p = 0; p < 32; p++) s += g_xpart[p * DMODEL + i];
    g_xsum[i] = s;
}

// colsum_d = Wv[d,:] . xsum  (exact fp32); grid 1024, block 128
__global__ void colvec_kernel(const float* __restrict__ Wv)
{
    __shared__ float red[128];
    const int d = blockIdx.x;
    float s = 0.f;
    for (int i = threadIdx.x; i < DMODEL; i += 128)
        s += Wv[(size_t)d * DMODEL + i] * g_xsum[i];
    red[threadIdx.x] = s;
    __syncthreads();
    for (int st = 64; st > 0; st >>= 1) {
        if (threadIdx.x < st) red[threadIdx.x] += red[threadIdx.x + st];
        __syncthreads();
    }
    if (threadIdx.x == 0) g_colsum[d] = red[0];
}

// w[k] = G[k,:] . xsum ; grid 1024, block 128 (G bf16 row-major)
__global__ void wvec_kernel(const __nv_bfloat16* __restrict__ G)
{
    __shared__ float red[128];
    const int k = blockIdx.x;
    float s = 0.f;
    for (int i = threadIdx.x; i < DMODEL; i += 128)
        s += __bfloat162float(G[(size_t)k * DMODEL + i]) * g_xsum[i];
    red[threadIdx.x] = s;
    __syncthreads();
    for (int st = 64; st > 0; st >>= 1) {
        if (threadIdx.x < st) red[threadIdx.x] += red[threadIdx.x + st];
        __syncthreads();
    }
    if (threadIdx.x == 0) g_w[k] = red[0];
}

// rowsum_r = (x_r . w) / 8192 ; one warp per row, 8 rows per block
__global__ void rowsum_kernel(const __nv_bfloat16* __restrict__ xb)
{
    const int row  = blockIdx.x * 8 + (threadIdx.x >> 5);
    const int lane = threadIdx.x & 31;
    const uint2* p = (const uint2*)(xb + (size_t)row * DMODEL);
    float s = 0.f;
    #pragma unroll
    for (int j = lane; j < 256; j += 32) {          // uint2 = 4 bf16
        uint2 u = p[j];
        float4 ws = ((const float4*)g_w)[j];
        s += __uint_as_float(u.x << 16) * ws.x;
        s += __uint_as_float(u.x & 0xFFFF0000u) * ws.y;
        s += __uint_as_float(u.y << 16) * ws.z;
        s += __uint_as_float(u.y & 0xFFFF0000u) * ws.w;
    }
    #pragma unroll
    for (int o = 16; o > 0; o >>= 1) s += __shfl_xor_sync(~0u, s, o);
    if (lane == 0) g_rowsum[row] = s * (1.f / 8192.f);
}

// ---------------------------------------------------------------------------
// launch: fork-join two-stream graph
// ---------------------------------------------------------------------------
extern "C" void kernel_launch(void* const* d_in, const int* in_sizes, int n_in,
                              void* d_out, int out_size)
{
    const float* x  = (const float*)d_in[0];
    const float* Wq = (const float*)d_in[1];
    const float* Wk = (const float*)d_in[2];
    const float* Wv = (const float*)d_in[3];
    float* out = (float*)d_out;

    __nv_bfloat16 *xb, *xtb, *wqt, *wkt, *wvb, *gg, *xtx, *ht, *mt;
    float *part, *partB;
    cudaGetSymbolAddress((void**)&xb,    g_xb);
    cudaGetSymbolAddress((void**)&xtb,   g_xtb);
    cudaGetSymbolAddress((void**)&wqt,   g_wqt);
    cudaGetSymbolAddress((void**)&wkt,   g_wkt);
    cudaGetSymbolAddress((void**)&wvb,   g_wvb);
    cudaGetSymbolAddress((void**)&gg,    g_g);
    cudaGetSymbolAddress((void**)&xtx,   g_xtx);
    cudaGetSymbolAddress((void**)&ht,    g_ht);
    cudaGetSymbolAddress((void**)&mt,    g_mt);
    cudaGetSymbolAddress((void**)&part,  g_part);
    cudaGetSymbolAddress((void**)&partB, g_partB);

    static bool init_done = false;
    static cudaStream_t s1;
    static cudaEvent_t evFork, evWvb, evG, evSide;
    if (!init_done) {
        cudaFuncSetAttribute(gemm_nt<2>, cudaFuncAttributeMaxDynamicSharedMemorySize, SMEM_TOTAL);
        cudaFuncSetAttribute(gemm_nt<4>, cudaFuncAttributeMaxDynamicSharedMemorySize, SMEM_TOTAL);
        cudaFuncSetAttribute(gemm_syrk128, cudaFuncAttributeMaxDynamicSharedMemorySize, SYRK_SMEM);
        cudaStreamCreateWithFlags(&s1, cudaStreamNonBlocking);
        cudaEventCreateWithFlags(&evFork, cudaEventDisableTiming);
        cudaEventCreateWithFlags(&evWvb,  cudaEventDisableTiming);
        cudaEventCreateWithFlags(&evG,    cudaEventDisableTiming);
        cudaEventCreateWithFlags(&evSide, cudaEventDisableTiming);
        init_done = true;
    }

    const dim3 blk(256);

    // ---- fork ----
    cudaEventRecord(evFork, 0);
    cudaStreamWaitEvent(s1, evFork, 0);

    // ======================= side stream (s1) =======================
    cvt_f32_bf16<<<DMODEL * DMODEL / 4 / 256, 256, 0, s1>>>(Wv, wvb, DMODEL * DMODEL / 4);
    cudaEventRecord(evWvb, s1);
    cvt_x_sum<<<dim3(4, 32), 256, 0, s1>>>(x, xb);
    cvt_transpose<<<dim3(32, 32), dim3(32, 8), 0, s1>>>(Wq, wqt, DMODEL, DMODEL);
    cvt_transpose<<<dim3(32, 32), dim3(32, 8), 0, s1>>>(Wk, wkt, DMODEL, DMODEL);
    // G = NT(wqt, wkt): G[k,j] = sum_d Wq[d,k] Wk[d,j], split-K 4 (partB)
    gemm_nt<4><<<dim3(4, 8, 4), blk, SMEM_TOTAL, s1>>>(
        wqt, wkt, partB, DMODEL, DMODEL, 256, DMODEL, 1.0f);
    reduce_partials<<<4096, 256, 0, s1>>>(partB, gg, DMODEL * DMODEL, 4);
    cudaEventRecord(evG, s1);
    reduce_xsum<<<4, 256, 0, s1>>>();
    colvec_kernel<<<1024, 128, 0, s1>>>(Wv);
    wvec_kernel<<<1024, 128, 0, s1>>>(gg);
    rowsum_kernel<<<NROWS / 8, 256, 0, s1>>>(xb);
    cudaEventRecord(evSide, s1);

    // ======================= main stream (critical path) =======================
    cvt_transpose<<<dim3(DMODEL / 32, NROWS / 32), dim3(32, 8)>>>(x, xtb, NROWS, DMODEL);
    // xtx = NT(xtb, xtb): 128x128 SYRK tiles (y>=x), z=4 -> 144 CTAs = 1 wave
    gemm_syrk128<<<dim3(8, 8, 4), blk, SYRK_SMEM>>>(xtb, part, NROWS / 4);
    // fused reduce + mirror
    reduce_mirror_xtx<<<dim3(32, 32), dim3(32, 8)>>>(part, xtx);
    // Ht = NT(wvb, xtx): ht[d,i] = (Wv x^T x)[d,i] = H[i,d]
    cudaStreamWaitEvent(0, evWvb, 0);
    gemm_nt<4><<<dim3(4, 8, 4), blk, SMEM_TOTAL>>>(
        wvb, xtx, part, DMODEL, DMODEL, 256, DMODEL, 1.0f);
    reduce_partials<<<4096, 256>>>(part, ht, DMODEL * DMODEL, 4);
    // Mt = NT(ht, gg): mt[d,k] = sum_i H[i,d] G[k,i] = (G H)[k,d] = M^T
    cudaStreamWaitEvent(0, evG, 0);
    gemm_nt<4><<<dim3(4, 8, 4), blk, SMEM_TOTAL>>>(
        ht, gg, part, DMODEL, DMODEL, 256, DMODEL, 1.0f);
    reduce_partials<<<4096, 256>>>(part, mt, DMODEL * DMODEL, 4);
    // join side stream, then final GEMM with affine epilogue
    cudaStreamWaitEvent(0, evSide, 0);
    gemm_nt<2><<<dim3(4, 64, 1), blk, SMEM_TOTAL>>>(
        xb, mt, out, NROWS, DMODEL, DMODEL, DMODEL, 1.0f / 8192.0f);
}

// round 17
// speedup vs baseline: 1.0729x; 1.0048x over previous
#include <cuda_runtime.h>
#include <cuda_bf16.h>
#include <cstdint>
#include <cstddef>

// ============================================================================
// ClassicalAttentionLayer, round 17: R16 + Programmatic Dependent Launch on
// the critical chain (pre-launch dependents, griddepcontrol.wait for data).
//   out[r,d] = (colsum_d + (x @ M)[r,d]/8192) / (8192 + rowsum_r)
//   M = G H,  G = Wq^T Wk,  H = (x^T x) Wv^T
//   rowsum_r = x_r . w / 8192,  w = G xsum
//   colsum = Wv @ xsum (exact fp32), xsum = column sums of x (exact fp32)
// Critical path (stream 0): cvt_transpose(x) -> xtx(syrk128) ->
// reduce+mirror -> Ht -> reduce -> Mt -> reduce -> final.  All links PDL.
// Side: conversions, stats, G.
// ============================================================================

#define NROWS 8192
#define DMODEL 1024

__device__ __nv_bfloat16 g_xb [(size_t)NROWS * DMODEL];   // x bf16 row-major
__device__ __nv_bfloat16 g_xtb[(size_t)DMODEL * NROWS];   // x^T bf16
__device__ __nv_bfloat16 g_wqt[(size_t)DMODEL * DMODEL];  // Wq^T
__device__ __nv_bfloat16 g_wkt[(size_t)DMODEL * DMODEL];  // Wk^T
__device__ __nv_bfloat16 g_wvb[(size_t)DMODEL * DMODEL];  // Wv
__device__ __nv_bfloat16 g_g  [(size_t)DMODEL * DMODEL];  // G row-major
__device__ __nv_bfloat16 g_xtx[(size_t)DMODEL * DMODEL];  // x^T x
__device__ __nv_bfloat16 g_ht [(size_t)DMODEL * DMODEL];  // H^T row-major
__device__ __nv_bfloat16 g_mt [(size_t)DMODEL * DMODEL];  // M^T row-major
__device__ float g_part [(size_t)8 * DMODEL * DMODEL];    // split-K partials (main)
__device__ float g_partB[(size_t)4 * DMODEL * DMODEL];    // split-K partials (side)
__device__ float g_rowsum[NROWS];
__device__ float g_xpart[32 * DMODEL];
__device__ float g_xsum[DMODEL];
__device__ float g_colsum[DMODEL];
__device__ float g_w[DMODEL];

// ---------------------------------------------------------------------------
// helpers (baseline <= sm_90 PTX features only -- must compile for sm_103)
// ---------------------------------------------------------------------------
__device__ __forceinline__ void gdc_wait() {
    asm volatile("griddepcontrol.wait;" ::: "memory");
}
__device__ __forceinline__ uint32_t smem_u32(const void* p) {
    uint32_t a;
    asm("{ .reg .u64 t; cvta.to.shared.u64 t, %1; cvt.u32.u64 %0, t; }"
        : "=r"(a) : "l"(p));
    return a;
}
__device__ __forceinline__ void ldsm4(uint32_t* r, uint32_t addr) {
    asm volatile("ldmatrix.sync.aligned.m8n8.x4.shared.b16 {%0,%1,%2,%3}, [%4];"
                 : "=r"(r[0]), "=r"(r[1]), "=r"(r[2]), "=r"(r[3]) : "r"(addr));
}
__device__ __forceinline__ void mma_bf16(float* d, const uint32_t* a,
                                         const uint32_t* b) {
    asm volatile(
        "mma.sync.aligned.m16n8k16.row.col.f32.bf16.bf16.f32 "
        "{%0,%1,%2,%3}, {%4,%5,%6,%7}, {%8,%9}, {%0,%1,%2,%3};"
        : "+f"(d[0]), "+f"(d[1]), "+f"(d[2]), "+f"(d[3])
        : "r"(a[0]), "r"(a[1]), "r"(a[2]), "r"(a[3]), "r"(b[0]), "r"(b[1]));
}
__device__ __forceinline__ void cp16(uint32_t d, const void* s) {
    asm volatile("cp.async.cg.shared.global [%0], [%1], 16;"
                 :: "r"(d), "l"(s) : "memory");
}
#define CP_COMMIT() asm volatile("cp.async.commit_group;" ::: "memory")
#define CP_WAIT1()  asm volatile("cp.async.wait_group 1;" ::: "memory")
#define SWZ(o) ((o) ^ (((o) >> 3) & 0x70))

__device__ __forceinline__ uint32_t pack_bf16x2(float lo, float hi) {
    uint32_t r;
    asm("cvt.rn.bf16x2.f32 %0, %1, %2;" : "=r"(r) : "f"(hi), "f"(lo));
    return r;
}

// ---------------------------------------------------------------------------
// bf16 NT GEMM: C = alpha * A[M,K_full] * B[N,K_full]^T (K-major, lda=K_full)
// CTA computes depth slice [z*K,(z+1)*K), z=blockIdx.z.
// CTA tile 128x256, BK=64, 3-stage cp.async, 8 warps, warp tile 64x64.
// MODE 2: C fp32 + linearized-softmax epilogue (grid.z==1).
// MODE 4: C fp32 raw partials at Cv + z*M*N.
// ---------------------------------------------------------------------------
#define STAGE_BYTES 49152
#define SMEM_TOTAL (3 * STAGE_BYTES)

template <int MODE>
__global__ __launch_bounds__(256, 1)
void gemm_nt(const __nv_bfloat16* __restrict__ A,
             const __nv_bfloat16* __restrict__ B,
             void* __restrict__ Cv, int M, int N, int K, int lda, float alpha)
{
    extern __shared__ char smem[];
    const uint32_t sb = smem_u32(smem);
    const int tid = threadIdx.x, lane = tid & 31, wid = tid >> 5;
    const int wm = wid >> 2, wn = wid & 3;
    const int m0 = blockIdx.y * 128, n0 = blockIdx.x * 256;
    const size_t zoff = (size_t)blockIdx.z * K;

    const int lrow = tid >> 3;
    const int lseg = (tid & 7) * 16;
    const char* Ag = (const char*)A + ((size_t)(m0 + lrow) * lda + zoff) * 2 + lseg;
    const char* Bg = (const char*)B + ((size_t)(n0 + lrow) * lda + zoff) * 2 + lseg;
    const size_t rstep = (size_t)32 * lda * 2;
    uint32_t soffA[4], soffB[8];
    #pragma unroll
    for (int i = 0; i < 4; i++)
        soffA[i] = SWZ((uint32_t)((lrow + 32 * i) * 128 + lseg));
    #pragma unroll
    for (int i = 0; i < 8; i++)
        soffB[i] = 16384u + SWZ((uint32_t)((lrow + 32 * i) * 128 + lseg));

    gdc_wait();   // PDL: block until same-stream producer's output is visible

    const int nch = K / 64;
    #pragma unroll
    for (int s = 0; s < 2; s++) {
        const uint32_t st = sb + s * STAGE_BYTES;
        #pragma unroll
        for (int i = 0; i < 4; i++) cp16(st + soffA[i], Ag + (size_t)s * 128 + i * rstep);
        #pragma unroll
        for (int i = 0; i < 8; i++) cp16(st + soffB[i], Bg + (size_t)s * 128 + i * rstep);
        CP_COMMIT();
    }

    float acc[4][8][4] = {};
    const int a_r  = wm * 64 + (lane & 15);
    const int a_kb = ((lane >> 4) & 1) * 16;
    const int b_r  = wn * 64 + ((lane >> 4) & 1) * 8 + (lane & 7);
    const int b_kb = ((lane >> 3) & 1) * 16;

    for (int c = 0; c < nch; c++) {
        CP_WAIT1();
        __syncthreads();
        if (c + 2 < nch) {
            const uint32_t st = sb + ((c + 2) % 3) * STAGE_BYTES;
            #pragma unroll
            for (int i = 0; i < 4; i++)
                cp16(st + soffA[i], Ag + (size_t)(c + 2) * 128 + i * rstep);
            #pragma unroll
            for (int i = 0; i < 8; i++)
                cp16(st + soffB[i], Bg + (size_t)(c + 2) * 128 + i * rstep);
        }
        CP_COMMIT();

        const uint32_t Ab = sb + (c % 3) * STAGE_BYTES;
        const uint32_t Bb = Ab + 16384;
        #pragma unroll
        for (int ks = 0; ks < 4; ks++) {
            uint32_t ah[4][4], bh[4][4];
            #pragma unroll
            for (int mt = 0; mt < 4; mt++)
                ldsm4(ah[mt], Ab + SWZ((uint32_t)((a_r + mt * 16) * 128 + ks * 32 + a_kb)));
            #pragma unroll
            for (int np = 0; np < 4; np++)
                ldsm4(bh[np], Bb + SWZ((uint32_t)((b_r + np * 16) * 128 + ks * 32 + b_kb)));
            #pragma unroll
            for (int mt = 0; mt < 4; mt++)
                #pragma unroll
                for (int nt = 0; nt < 8; nt++)
                    mma_bf16(acc[mt][nt], ah[mt], &bh[nt >> 1][(nt & 1) * 2]);
        }
    }

    // ------------------------------ epilogue ------------------------------
    if (MODE == 2) {
        float* C = (float*)Cv;
        #pragma unroll
        for (int mt = 0; mt < 4; mt++) {
            const int r0 = m0 + wm * 64 + mt * 16 + (lane >> 2);
            const float c0 = 1.f / (8192.f + g_rowsum[r0]);
            const float c1 = 1.f / (8192.f + g_rowsum[r0 + 8]);
            #pragma unroll
            for (int nt = 0; nt < 8; nt++) {
                const int col = n0 + wn * 64 + nt * 8 + (lane & 3) * 2;
                const float2 cs = *(const float2*)&g_colsum[col];
                float2 o0, o1;
                o0.x = c0 * (acc[mt][nt][0] * alpha + cs.x);
                o0.y = c0 * (acc[mt][nt][1] * alpha + cs.y);
                o1.x = c1 * (acc[mt][nt][2] * alpha + cs.x);
                o1.y = c1 * (acc[mt][nt][3] * alpha + cs.y);
                *(float2*)(C + (size_t)r0 * N + col)       = o0;
                *(float2*)(C + (size_t)(r0 + 8) * N + col) = o1;
            }
        }
    }
    if (MODE == 4) {
        float* C = (float*)Cv + (size_t)blockIdx.z * M * N;
        #pragma unroll
        for (int mt = 0; mt < 4; mt++) {
            const int r0 = m0 + wm * 64 + mt * 16 + (lane >> 2);
            #pragma unroll
            for (int nt = 0; nt < 8; nt++) {
                const int col = n0 + wn * 64 + nt * 8 + (lane & 3) * 2;
                *(float2*)(C + (size_t)r0 * N + col) =
                    make_float2(acc[mt][nt][0], acc[mt][nt][1]);
                *(float2*)(C + (size_t)(r0 + 8) * N + col) =
                    make_float2(acc[mt][nt][2], acc[mt][nt][3]);
            }
        }
    }
}

// ---------------------------------------------------------------------------
// SYRK kernel for xtx: 128x128 CTA tile, lower-triangle tiles only
// (blockIdx.y >= blockIdx.x), split-K via blockIdx.z (z=4, K=2048/slice).
// 8 warps (2x4), warp tile 64x32, BK=64, 3-stage cp.async (96 KB smem).
// ---------------------------------------------------------------------------
#define SYRK_STAGE 32768
#define SYRK_SMEM (3 * SYRK_STAGE)   // 98304

__global__ __launch_bounds__(256, 1)
void gemm_syrk128(const __nv_bfloat16* __restrict__ A,
                  float* __restrict__ part, int K)
{
    if ((int)blockIdx.y < (int)blockIdx.x) { gdc_wait(); return; }

    extern __shared__ char smem[];
    const uint32_t sb = smem_u32(smem);
    const int tid = threadIdx.x, lane = tid & 31, wid = tid >> 5;
    const int wm = wid >> 2, wn = wid & 3;
    const int m0 = blockIdx.y * 128, n0 = blockIdx.x * 128;
    const size_t zoff = (size_t)blockIdx.z * K;
    const int lda = NROWS;

    const int lrow = tid >> 3;
    const int lseg = (tid & 7) * 16;
    const char* Ag = (const char*)A + ((size_t)(m0 + lrow) * lda + zoff) * 2 + lseg;
    const char* Bg = (const char*)A + ((size_t)(n0 + lrow) * lda + zoff) * 2 + lseg;
    const size_t rstep = (size_t)32 * lda * 2;
    uint32_t soff[4];
    #pragma unroll
    for (int i = 0; i < 4; i++)
        soff[i] = SWZ((uint32_t)((lrow + 32 * i) * 128 + lseg));

    gdc_wait();   // PDL: xtb must be written by cvt_transpose

    const int nch = K / 64;
    #pragma unroll
    for (int s = 0; s < 2; s++) {
        const uint32_t st = sb + s * SYRK_STAGE;
        #pragma unroll
        for (int i = 0; i < 4; i++) cp16(st + soff[i],          Ag + (size_t)s * 128 + i * rstep);
        #pragma unroll
        for (int i = 0; i < 4; i++) cp16(st + 16384u + soff[i], Bg + (size_t)s * 128 + i * rstep);
        CP_COMMIT();
    }

    float acc[4][4][4] = {};
    const int a_r  = wm * 64 + (lane & 15);
    const int a_kb = ((lane >> 4) & 1) * 16;
    const int b_r  = wn * 32 + ((lane >> 4) & 1) * 8 + (lane & 7);
    const int b_kb = ((lane >> 3) & 1) * 16;

    for (int c = 0; c < nch; c++) {
        CP_WAIT1();
        __syncthreads();
        if (c + 2 < nch) {
            const uint32_t st = sb + ((c + 2) % 3) * SYRK_STAGE;
            #pragma unroll
            for (int i = 0; i < 4; i++)
                cp16(st + soff[i],          Ag + (size_t)(c + 2) * 128 + i * rstep);
            #pragma unroll
            for (int i = 0; i < 4; i++)
                cp16(st + 16384u + soff[i], Bg + (size_t)(c + 2) * 128 + i * rstep);
        }
        CP_COMMIT();

        const uint32_t Ab = sb + (c % 3) * SYRK_STAGE;
        const uint32_t Bb = Ab + 16384;
        #pragma unroll
        for (int ks = 0; ks < 4; ks++) {
            uint32_t ah[4][4], bh[2][4];
            #pragma unroll
            for (int mt = 0; mt < 4; mt++)
                ldsm4(ah[mt], Ab + SWZ((uint32_t)((a_r + mt * 16) * 128 + ks * 32 + a_kb)));
            #pragma unroll
            for (int np = 0; np < 2; np++)
                ldsm4(bh[np], Bb + SWZ((uint32_t)((b_r + np * 16) * 128 + ks * 32 + b_kb)));
            #pragma unroll
            for (int mt = 0; mt < 4; mt++)
                #pragma unroll
                for (int nt = 0; nt < 4; nt++)
                    mma_bf16(acc[mt][nt], ah[mt], &bh[nt >> 1][(nt & 1) * 2]);
        }
    }

    float* P = part + (size_t)blockIdx.z * DMODEL * DMODEL;
    #pragma unroll
    for (int mt = 0; mt < 4; mt++) {
        const int r0 = m0 + wm * 64 + mt * 16 + (lane >> 2);
        #pragma unroll
        for (int nt = 0; nt < 4; nt++) {
            const int col = n0 + wn * 32 + nt * 8 + (lane & 3) * 2;
            *(float2*)(P + (size_t)r0 * DMODEL + col) =
                make_float2(acc[mt][nt][0], acc[mt][nt][1]);
            *(float2*)(P + (size_t)(r0 + 8) * DMODEL + col) =
                make_float2(acc[mt][nt][2], acc[mt][nt][3]);
        }
    }
}

// ---------------------------------------------------------------------------
// small kernels
// ---------------------------------------------------------------------------
// fused: xb = bf16(x) and per-256-row column partial sums. grid (4,32), blk 256
__global__ void cvt_x_sum(const float* __restrict__ x,
                          __nv_bfloat16* __restrict__ xb)
{
    const int col = blockIdx.x * 256 + threadIdx.x;
    const int r0  = blockIdx.y * 256;
    float s = 0.f;
    #pragma unroll 4
    for (int j = 0; j < 256; j++) {
        float f = x[(size_t)(r0 + j) * DMODEL + col];
        s += f;
        xb[(size_t)(r0 + j) * DMODEL + col] = __float2bfloat16(f);
    }
    g_xpart[blockIdx.y * DMODEL + col] = s;
}

__global__ void cvt_f32_bf16(const float* __restrict__ src,
                             __nv_bfloat16* __restrict__ dst, int n4)
{
    int i = blockIdx.x * blockDim.x + threadIdx.x;
    if (i < n4) {
        float4 f = ((const float4*)src)[i];
        uint2 o;
        o.x = pack_bf16x2(f.x, f.y);
        o.y = pack_bf16x2(f.z, f.w);
        ((uint2*)dst)[i] = o;
    }
}

// transpose-convert: dst[c,r] = bf16(src[r,c]); src [R,C] fp32. grid (C/32,R/32)
__global__ void cvt_transpose(const float* __restrict__ src,
                              __nv_bfloat16* __restrict__ dst, int R, int C)
{
    __shared__ float tile[32][33];
    const int x0 = blockIdx.x * 32, y0 = blockIdx.y * 32;
    #pragma unroll
    for (int i = 0; i < 4; i++)
        tile[threadIdx.y + i * 8][threadIdx.x] =
            src[(size_t)(y0 + threadIdx.y + i * 8) * C + x0 + threadIdx.x];
    __syncthreads();
    #pragma unroll
    for (int i = 0; i < 4; i++)
        dst[(size_t)(x0 + threadIdx.y + i * 8) * R + y0 + threadIdx.x] =
            __float2bfloat16(tile[threadIdx.x][threadIdx.y + i * 8]);
}

// fused reduce (z=4 split-K partials) + mirror for xtx. grid (32,32), blk (32,8)
__global__ void reduce_mirror_xtx(const float* __restrict__ part,
                                  __nv_bfloat16* __restrict__ xtx)
{
    const int m0 = blockIdx.y * 32, n0 = blockIdx.x * 32;
    gdc_wait();   // PDL: partials from syrk
    if ((m0 >> 7) < (n0 >> 7)) return;   // upper region: filled by mirror
    __shared__ __nv_bfloat16 t[32][33];
    const int tx = threadIdx.x, ty = threadIdx.y;
    #pragma unroll
    for (int i = 0; i < 4; i++) {
        const int row = m0 + ty + i * 8;
        const size_t idx = (size_t)row * DMODEL + n0 + tx;
        float s = part[idx] + part[idx + (size_t)DMODEL * DMODEL]
                + part[idx + 2 * (size_t)DMODEL * DMODEL]
                + part[idx + 3 * (size_t)DMODEL * DMODEL];
        __nv_bfloat16 v = __float2bfloat16(s);
        xtx[idx] = v;
        t[ty + i * 8][tx] = v;
    }
    if ((m0 >> 7) > (n0 >> 7)) {
        __syncthreads();
        #pragma unroll
        for (int i = 0; i < 4; i++)
            xtx[(size_t)(n0 + ty + i * 8) * DMODEL + m0 + tx] = t[tx][ty + i * 8];
    }
}

// reduce split-K fp32 partials -> bf16
__global__ void reduce_partials(const float* __restrict__ part,
                                __nv_bfloat16* __restrict__ dst, int n, int z)
{
    int i = blockIdx.x * 256 + threadIdx.x;
    gdc_wait();   // no-op when launched without PDL attribute
    if (i < n) {
        float s = 0.f;
        for (int zz = 0; zz < z; zz++) s += part[(size_t)zz * n + i];
        dst[i] = __float2bfloat16(s);
    }
}

__global__ void reduce_xsum()
{
    const int i = blockIdx.x * 256 + threadIdx.x;   // grid 4
    float s = 0.f;
    #pragma unroll
    for (int p = 0; p < 32; p++) s += g_xpart[p * DMODEL + i];
    g_xsum[i] = s;
}

// colsum_d = Wv[d,:] . xsum  (exact fp32); grid 1024, block 128
__global__ void colvec_kernel(const float* __restrict__ Wv)
{
    __shared__ float red[128];
    const int d = blockIdx.x;
    float s = 0.f;
    for (int i = threadIdx.x; i < DMODEL; i += 128)
        s += Wv[(size_t)d * DMODEL + i] * g_xsum[i];
    red[threadIdx.x] = s;
    __syncthreads();
    for (int st = 64; st > 0; st >>= 1) {
        if (threadIdx.x < st) red[threadIdx.x] += red[threadIdx.x + st];
        __syncthreads();
    }
    if (threadIdx.x == 0) g_colsum[d] = red[0];
}

// w[k] = G[k,:] . xsum ; grid 1024, block 128 (G bf16 row-major)
__global__ void wvec_kernel(const __nv_bfloat16* __restrict__ G)
{
    __shared__ float red[128];
    const int k = blockIdx.x;
    float s = 0.f;
    for (int i = threadIdx.x; i < DMODEL; i += 128)
        s += __bfloat162float(G[(size_t)k * DMODEL + i]) * g_xsum[i];
    red[threadIdx.x] = s;
    __syncthreads();
    for (int st = 64; st > 0; st >>= 1) {
        if (threadIdx.x < st) red[threadIdx.x] += red[threadIdx.x + st];
        __syncthreads();
    }
    if (threadIdx.x == 0) g_w[k] = red[0];
}

// rowsum_r = (x_r . w) / 8192 ; one warp per row, 8 rows per block
__global__ void rowsum_kernel(const __nv_bfloat16* __restrict__ xb)
{
    const int row  = blockIdx.x * 8 + (threadIdx.x >> 5);
    const int lane = threadIdx.x & 31;
    const uint2* p = (const uint2*)(xb + (size_t)row * DMODEL);
    float s = 0.f;
    #pragma unroll
    for (int j = lane; j < 256; j += 32) {          // uint2 = 4 bf16
        uint2 u = p[j];
        float4 ws = ((const float4*)g_w)[j];
        s += __uint_as_float(u.x << 16) * ws.x;
        s += __uint_as_float(u.x & 0xFFFF0000u) * ws.y;
        s += __uint_as_float(u.y << 16) * ws.z;
        s += __uint_as_float(u.y & 0xFFFF0000u) * ws.w;
    }
    #pragma unroll
    for (int o = 16; o > 0; o >>= 1) s += __shfl_xor_sync(~0u, s, o);
    if (lane == 0) g_rowsum[row] = s * (1.f / 8192.f);
}

// ---------------------------------------------------------------------------
// PDL launch helper
// ---------------------------------------------------------------------------
static void launch_pdl(const void* fn, dim3 grid, dim3 block, size_t smem,
                       cudaStream_t st, void** args)
{
    cudaLaunchConfig_t cfg = {};
    cfg.gridDim = grid;
    cfg.blockDim = block;
    cfg.dynamicSmemBytes = smem;
    cfg.stream = st;
    cudaLaunchAttribute attr[1];
    attr[0].id = cudaLaunchAttributeProgrammaticStreamSerialization;
    attr[0].val.programmaticStreamSerializationAllowed = 1;
    cfg.attrs = attr;
    cfg.numAttrs = 1;
    cudaLaunchKernelExC(&cfg, fn, args);
}

// ---------------------------------------------------------------------------
// launch: fork-join two-stream graph; PDL on main-stream chain
// ---------------------------------------------------------------------------
extern "C" void kernel_launch(void* const* d_in, const int* in_sizes, int n_in,
                              void* d_out, int out_size)
{
    const float* x  = (const float*)d_in[0];
    const float* Wq = (const float*)d_in[1];
    const float* Wk = (const float*)d_in[2];
    const float* Wv = (const float*)d_in[3];
    float* out = (float*)d_out;

    __nv_bfloat16 *xb, *xtb, *wqt, *wkt, *wvb, *gg, *xtx, *ht, *mt;
    float *part, *partB;
    cudaGetSymbolAddress((void**)&xb,    g_xb);
    cudaGetSymbolAddress((void**)&xtb,   g_xtb);
    cudaGetSymbolAddress((void**)&wqt,   g_wqt);
    cudaGetSymbolAddress((void**)&wkt,   g_wkt);
    cudaGetSymbolAddress((void**)&wvb,   g_wvb);
    cudaGetSymbolAddress((void**)&gg,    g_g);
    cudaGetSymbolAddress((void**)&xtx,   g_xtx);
    cudaGetSymbolAddress((void**)&ht,    g_ht);
    cudaGetSymbolAddress((void**)&mt,    g_mt);
    cudaGetSymbolAddress((void**)&part,  g_part);
    cudaGetSymbolAddress((void**)&partB, g_partB);

    static bool init_done = false;
    static cudaStream_t s1;
    static cudaEvent_t evFork, evWvb, evG, evSide;
    if (!init_done) {
        cudaFuncSetAttribute(gemm_nt<2>, cudaFuncAttributeMaxDynamicSharedMemorySize, SMEM_TOTAL);
        cudaFuncSetAttribute(gemm_nt<4>, cudaFuncAttributeMaxDynamicSharedMemorySize, SMEM_TOTAL);
        cudaFuncSetAttribute(gemm_syrk128, cudaFuncAttributeMaxDynamicSharedMemorySize, SYRK_SMEM);
        cudaStreamCreateWithFlags(&s1, cudaStreamNonBlocking);
        cudaEventCreateWithFlags(&evFork, cudaEventDisableTiming);
        cudaEventCreateWithFlags(&evWvb,  cudaEventDisableTiming);
        cudaEventCreateWithFlags(&evG,    cudaEventDisableTiming);
        cudaEventCreateWithFlags(&evSide, cudaEventDisableTiming);
        init_done = true;
    }

    const dim3 blk(256);

    // ---- fork ----
    cudaEventRecord(evFork, 0);
    cudaStreamWaitEvent(s1, evFork, 0);

    // ======================= side stream (s1) =======================
    cvt_f32_bf16<<<DMODEL * DMODEL / 4 / 256, 256, 0, s1>>>(Wv, wvb, DMODEL * DMODEL / 4);
    cudaEventRecord(evWvb, s1);
    cvt_x_sum<<<dim3(4, 32), 256, 0, s1>>>(x, xb);
    cvt_transpose<<<dim3(32, 32), dim3(32, 8), 0, s1>>>(Wq, wqt, DMODEL, DMODEL);
    cvt_transpose<<<dim3(32, 32), dim3(32, 8), 0, s1>>>(Wk, wkt, DMODEL, DMODEL);
    // G = NT(wqt, wkt): G[k,j] = sum_d Wq[d,k] Wk[d,j], split-K 4 (partB)
    gemm_nt<4><<<dim3(4, 8, 4), blk, SMEM_TOTAL, s1>>>(
        wqt, wkt, partB, DMODEL, DMODEL, 256, DMODEL, 1.0f);
    reduce_partials<<<4096, 256, 0, s1>>>(partB, gg, DMODEL * DMODEL, 4);
    cudaEventRecord(evG, s1);
    reduce_xsum<<<4, 256, 0, s1>>>();
    colvec_kernel<<<1024, 128, 0, s1>>>(Wv);
    wvec_kernel<<<1024, 128, 0, s1>>>(gg);
    rowsum_kernel<<<NROWS / 8, 256, 0, s1>>>(xb);
    cudaEventRecord(evSide, s1);

    // ======================= main stream (critical path, PDL chain) =========
    cvt_transpose<<<dim3(DMODEL / 32, NROWS / 32), dim3(32, 8)>>>(x, xtb, NROWS, DMODEL);

    // xtx = NT(xtb, xtb): 128x128 SYRK tiles (y>=x), z=4 -> 144 CTAs
    {
        int kk = NROWS / 4;
        void* args[] = {&xtb, &part, &kk};
        launch_pdl((const void*)gemm_syrk128, dim3(8, 8, 4), blk, SYRK_SMEM, 0, args);
    }
    // fused reduce + mirror
    {
        void* args[] = {&part, &xtx};
        launch_pdl((const void*)reduce_mirror_xtx, dim3(32, 32), dim3(32, 8), 0, 0, args);
    }
    // Ht = NT(wvb, xtx): ht[d,i] = (Wv x^T x)[d,i] = H[i,d]
    cudaStreamWaitEvent(0, evWvb, 0);
    {
        int M = DMODEL, N = DMODEL, K = 256, lda = DMODEL; float al = 1.0f;
        void* args[] = {&wvb, &xtx, (void*)&part, &M, &N, &K, &lda, &al};
        launch_pdl((const void*)gemm_nt<4>, dim3(4, 8, 4), blk, SMEM_TOTAL, 0, args);
    }
    {
        int n = DMODEL * DMODEL, z = 4;
        void* args[] = {&part, &ht, &n, &z};
        launch_pdl((const void*)reduce_partials, dim3(4096), dim3(256), 0, 0, args);
    }
    // Mt = NT(ht, gg): mt[d,k] = sum_i H[i,d] G[k,i] = (G H)[k,d] = M^T
    cudaStreamWaitEvent(0, evG, 0);
    {
        int M = DMODEL, N = DMODEL, K = 256, lda = DMODEL; float al = 1.0f;
        void* args[] = {&ht, &gg, (void*)&part, &M, &N, &K, &lda, &al};
        launch_pdl((const void*)gemm_nt<4>, dim3(4, 8, 4), blk, SMEM_TOTAL, 0, args);
    }
    {
        int n = DMODEL * DMODEL, z = 4;
        void* args[] = {&part, &mt, &n, &z};
        launch_pdl((const void*)reduce_partials, dim3(4096), dim3(256), 0, 0, args);
    }
    // join side stream, then final GEMM with affine epilogue
    cudaStreamWaitEvent(0, evSide, 0);
    {
        int M = NROWS, N = DMODEL, K = DMODEL, lda = DMODEL;
        float al = 1.0f / 8192.0f;
        void* outv = (void*)out;
        void* args[] = {&xb, &mt, &outv, &M, &N, &K, &lda, &al};
        launch_pdl((const void*)gemm_nt<2>, dim3(4, 64, 1), blk, SMEM_TOTAL, 0, args);
    }
}